// round 4
// baseline (speedup 1.0000x reference)
#include <cuda_runtime.h>
#include <cstdint>
#include <cstddef>

#define B_ 64
#define L_ 512
#define D_ 512
#define F_ 2048
#define E_ 8

__device__ float g_gates[B_ * E_];
__device__ float g_h[(size_t)B_ * E_ * L_ * F_];
// tf32-pre-rounded copies
__device__ float g_xr[(size_t)B_ * L_ * D_];
__device__ float g_w1r[(size_t)E_ * D_ * F_];
__device__ float g_w2r[(size_t)E_ * F_ * D_];

#define A_STRIDE 36
#define B_STRIDE 136
#define A_TILE (128 * A_STRIDE)
#define B_TILE (32 * B_STRIDE)
#define SMEM_FLOATS (2 * A_TILE + 2 * B_TILE)   // 71680 B

// ---------------------------------------------------------------------------
__device__ __forceinline__ uint32_t f2tf32(float x) {
    uint32_t r;
    asm("cvt.rna.tf32.f32 %0, %1;" : "=r"(r) : "f"(x));
    return r;
}

__device__ __forceinline__ void mma_tf32(float* d, const uint32_t* a, const uint32_t* b) {
    asm volatile(
        "mma.sync.aligned.m16n8k8.row.col.f32.tf32.tf32.f32 "
        "{%0,%1,%2,%3},{%4,%5,%6,%7},{%8,%9},{%0,%1,%2,%3};\n"
        : "+f"(d[0]), "+f"(d[1]), "+f"(d[2]), "+f"(d[3])
        : "r"(a[0]), "r"(a[1]), "r"(a[2]), "r"(a[3]),
          "r"(b[0]), "r"(b[1]));
}

__device__ __forceinline__ void cp16(void* smem_dst, const void* gsrc) {
    uint32_t s = (uint32_t)__cvta_generic_to_shared(smem_dst);
    asm volatile("cp.async.cg.shared.global [%0], [%1], 16;" :: "r"(s), "l"(gsrc));
}
#define CP_COMMIT() asm volatile("cp.async.commit_group;")
#define CP_WAIT1()  asm volatile("cp.async.wait_group 1;")
#define CP_WAIT0()  asm volatile("cp.async.wait_group 0;")

__device__ __forceinline__ float gelu_exact(float v) {
    return 0.5f * v * (1.0f + erff(v * 0.70710678118654752f));
}

// ---------------------------------------------------------------------------
// Kernel 0: pre-round x, w1, w2 to tf32 (RNA)
// ---------------------------------------------------------------------------
__global__ void preround_kernel(const float* __restrict__ x,
                                const float* __restrict__ w1,
                                const float* __restrict__ w2) {
    size_t i = (size_t)blockIdx.x * blockDim.x + threadIdx.x;
    size_t stride = (size_t)gridDim.x * blockDim.x;
    const size_t NX = (size_t)B_ * L_ * D_;
    const size_t NW = (size_t)E_ * D_ * F_;
    for (size_t j = i; j < NX; j += stride)
        g_xr[j] = __uint_as_float(f2tf32(x[j]));
    for (size_t j = i; j < NW; j += stride) {
        g_w1r[j] = __uint_as_float(f2tf32(w1[j]));
        g_w2r[j] = __uint_as_float(f2tf32(w2[j]));
    }
}

// ---------------------------------------------------------------------------
// Kernel 1: gates + guide loss
// ---------------------------------------------------------------------------
__global__ void gates_kernel(const float* __restrict__ logits,
                             const int* __restrict__ masks,
                             float* __restrict__ guide_out) {
    __shared__ float s_m[B_];
    int b = threadIdx.x;

    float v[E_];
    float mx = -1e30f;
#pragma unroll
    for (int e = 0; e < E_; ++e) {
        v[e] = logits[b * E_ + e];
        mx = fmaxf(mx, v[e]);
    }
    float s = 0.f;
#pragma unroll
    for (int e = 0; e < E_; ++e) { v[e] = expf(v[e] - mx); s += v[e]; }
    float inv = 1.0f / s;
    float g[E_];
    float msum = 0.f;
#pragma unroll
    for (int e = 0; e < E_; ++e) {
        float raw = v[e] * inv;
        float m = (masks[b * E_ + e] == 1) ? 1.0f : 0.0f;
        g[e] = raw * m;
        msum += g[e];
    }
    float inv2 = 1.0f / (msum + 1e-9f);
#pragma unroll
    for (int e = 0; e < E_; ++e) g_gates[b * E_ + e] = g[e] * inv2;

    s_m[b] = msum;
    __syncthreads();
    if (b == 0) {
        float t = 0.f;
        for (int i = 0; i < B_; ++i) t += s_m[i];
        float gl = 1.0f - t / (float)B_;
        guide_out[0] = gl * gl;
    }
}

// ---------------------------------------------------------------------------
// Kernel 2: h = tf32round(gelu(x @ w1 + b1))
// 256 threads, 8 warps, warp tile 32x64, block tile 128x128x32, 2-stage cp.async
// ---------------------------------------------------------------------------
__global__ __launch_bounds__(256, 2)
void gemm1_kernel(const float* __restrict__ b1) {
    int pair = blockIdx.z;
    if (g_gates[pair] == 0.0f) return;
    int b = pair >> 3;
    int e = pair & 7;
    int m0 = blockIdx.y * 128;
    int n0 = blockIdx.x * 128;

    extern __shared__ float sm[];
    float* As = sm;
    float* Bs = sm + 2 * A_TILE;

    const float* xb  = g_xr  + (size_t)b * L_ * D_;
    const float* w1e = g_w1r + (size_t)e * D_ * F_;

    int tid  = threadIdx.x;
    int lane = tid & 31;
    int warp = tid >> 5;               // 0..7
    int wm = (warp >> 1) * 32;         // 0,32,64,96
    int wn = (warp & 1) * 64;          // 0,64
    int mrow = lane >> 2;
    int kcol = lane & 3;

    int ar = tid >> 3, ac = (tid & 7) * 4;     // A loader: rows 0..31 (+i*32)
    int br = tid >> 5, bc = (tid & 31) * 4;    // B loader: rows 0..7 (+i*8)

    float acc[2][8][4];
#pragma unroll
    for (int mi = 0; mi < 2; ++mi)
#pragma unroll
        for (int ni = 0; ni < 8; ++ni)
#pragma unroll
            for (int r = 0; r < 4; ++r) acc[mi][ni][r] = 0.f;

    auto load_stage = [&](int s, int k0) {
        float* Ad = As + s * A_TILE;
        float* Bd = Bs + s * B_TILE;
#pragma unroll
        for (int i = 0; i < 4; ++i)
            cp16(&Ad[(ar + i * 32) * A_STRIDE + ac],
                 &xb[(size_t)(m0 + ar + i * 32) * D_ + k0 + ac]);
#pragma unroll
        for (int i = 0; i < 4; ++i)
            cp16(&Bd[(br + i * 8) * B_STRIDE + bc],
                 &w1e[(size_t)(k0 + br + i * 8) * F_ + n0 + bc]);
        CP_COMMIT();
    };

    load_stage(0, 0);
    int st = 0;
    for (int k0 = 0; k0 < D_; k0 += 32) {
        bool more = (k0 + 32 < D_);
        if (more) load_stage(st ^ 1, k0 + 32);
        if (more) CP_WAIT1(); else CP_WAIT0();
        __syncthreads();

        const float* Ac = As + st * A_TILE;
        const float* Bc = Bs + st * B_TILE;
#pragma unroll
        for (int kk = 0; kk < 32; kk += 8) {
            uint32_t af[2][4], bf[8][2];
#pragma unroll
            for (int mi = 0; mi < 2; ++mi) {
                int r = wm + mi * 16 + mrow;
                af[mi][0] = __float_as_uint(Ac[r * A_STRIDE + kk + kcol]);
                af[mi][1] = __float_as_uint(Ac[(r + 8) * A_STRIDE + kk + kcol]);
                af[mi][2] = __float_as_uint(Ac[r * A_STRIDE + kk + kcol + 4]);
                af[mi][3] = __float_as_uint(Ac[(r + 8) * A_STRIDE + kk + kcol + 4]);
            }
#pragma unroll
            for (int ni = 0; ni < 8; ++ni) {
                int c = wn + ni * 8 + mrow;
                bf[ni][0] = __float_as_uint(Bc[(kk + kcol) * B_STRIDE + c]);
                bf[ni][1] = __float_as_uint(Bc[(kk + kcol + 4) * B_STRIDE + c]);
            }
#pragma unroll
            for (int mi = 0; mi < 2; ++mi)
#pragma unroll
                for (int ni = 0; ni < 8; ++ni)
                    mma_tf32(acc[mi][ni], af[mi], bf[ni]);
        }
        __syncthreads();
        st ^= 1;
    }

    float* hout = g_h + (size_t)pair * L_ * F_;
    const float* b1e = b1 + e * F_;
#pragma unroll
    for (int mi = 0; mi < 2; ++mi) {
        int r0 = m0 + wm + mi * 16 + mrow;
#pragma unroll
        for (int ni = 0; ni < 8; ++ni) {
            int c0 = n0 + wn + ni * 8 + kcol * 2;
            float bias0 = b1e[c0], bias1 = b1e[c0 + 1];
            hout[(size_t)r0 * F_ + c0]           = __uint_as_float(f2tf32(gelu_exact(acc[mi][ni][0] + bias0)));
            hout[(size_t)r0 * F_ + c0 + 1]       = __uint_as_float(f2tf32(gelu_exact(acc[mi][ni][1] + bias1)));
            hout[(size_t)(r0 + 8) * F_ + c0]     = __uint_as_float(f2tf32(gelu_exact(acc[mi][ni][2] + bias0)));
            hout[(size_t)(r0 + 8) * F_ + c0 + 1] = __uint_as_float(f2tf32(gelu_exact(acc[mi][ni][3] + bias1)));
        }
    }
}

// ---------------------------------------------------------------------------
// Kernel 3: out = sum_e g*(h @ w2) + sum_e g*b2
// 256 threads, warp tile 32x64; gate via accumulator telescoping
// ---------------------------------------------------------------------------
__global__ __launch_bounds__(256, 2)
void gemm2_kernel(const float* __restrict__ b2,
                  float* __restrict__ out) {
    int b  = blockIdx.z;
    int m0 = blockIdx.y * 128;
    int n0 = blockIdx.x * 128;

    extern __shared__ float sm[];
    float* As = sm;
    float* Bs = sm + 2 * A_TILE;
    __shared__ float sbias[128];

    int tid  = threadIdx.x;
    int lane = tid & 31;
    int warp = tid >> 5;
    int wm = (warp >> 1) * 32;
    int wn = (warp & 1) * 64;
    int mrow = lane >> 2;
    int kcol = lane & 3;

    int ar = tid >> 3, ac = (tid & 7) * 4;
    int br = tid >> 5, bc = (tid & 31) * 4;

    int act[E_]; float gact[E_]; int nact = 0;
#pragma unroll
    for (int e = 0; e < E_; ++e) {
        float g = g_gates[b * E_ + e];
        if (g != 0.0f) { act[nact] = e; gact[nact] = g; ++nact; }
    }

    if (tid < 128) {
        float bias = 0.f;
        for (int i = 0; i < nact; ++i)
            bias += gact[i] * b2[act[i] * D_ + n0 + tid];
        sbias[tid] = bias;
    }
    __syncthreads();

    float acc[2][8][4];
#pragma unroll
    for (int mi = 0; mi < 2; ++mi)
#pragma unroll
        for (int ni = 0; ni < 8; ++ni)
#pragma unroll
            for (int r = 0; r < 4; ++r) acc[mi][ni][r] = 0.f;

    const int KITERS = F_ / 32;               // 64
    int total = nact * KITERS;

    auto load_stage = [&](int s, int t) {
        int ei = t >> 6;
        int k0 = (t & 63) << 5;
        const float* hptr = g_h + (size_t)(b * E_ + act[ei]) * L_ * F_;
        const float* w2e  = g_w2r + (size_t)act[ei] * F_ * D_;
        float* Ad = As + s * A_TILE;
        float* Bd = Bs + s * B_TILE;
#pragma unroll
        for (int i = 0; i < 4; ++i)
            cp16(&Ad[(ar + i * 32) * A_STRIDE + ac],
                 &hptr[(size_t)(m0 + ar + i * 32) * F_ + k0 + ac]);
#pragma unroll
        for (int i = 0; i < 4; ++i)
            cp16(&Bd[(br + i * 8) * B_STRIDE + bc],
                 &w2e[(size_t)(k0 + br + i * 8) * D_ + n0 + bc]);
        CP_COMMIT();
    };

    if (total > 0) {
        load_stage(0, 0);
        int st = 0;
        for (int t = 0; t < total; ++t) {
            bool more = (t + 1 < total);
            if (more) load_stage(st ^ 1, t + 1);
            if (more) CP_WAIT1(); else CP_WAIT0();
            __syncthreads();

            if ((t & 63) == 0 && t > 0) {
                int ei = t >> 6;
                float ratio = gact[ei - 1] / gact[ei];
#pragma unroll
                for (int mi = 0; mi < 2; ++mi)
#pragma unroll
                    for (int ni = 0; ni < 8; ++ni)
#pragma unroll
                        for (int r = 0; r < 4; ++r) acc[mi][ni][r] *= ratio;
            }

            const float* Ac = As + st * A_TILE;
            const float* Bc = Bs + st * B_TILE;
#pragma unroll
            for (int kk = 0; kk < 32; kk += 8) {
                uint32_t af[2][4], bf[8][2];
#pragma unroll
                for (int mi = 0; mi < 2; ++mi) {
                    int r = wm + mi * 16 + mrow;
                    af[mi][0] = __float_as_uint(Ac[r * A_STRIDE + kk + kcol]);
                    af[mi][1] = __float_as_uint(Ac[(r + 8) * A_STRIDE + kk + kcol]);
                    af[mi][2] = __float_as_uint(Ac[r * A_STRIDE + kk + kcol + 4]);
                    af[mi][3] = __float_as_uint(Ac[(r + 8) * A_STRIDE + kk + kcol + 4]);
                }
#pragma unroll
                for (int ni = 0; ni < 8; ++ni) {
                    int c = wn + ni * 8 + mrow;
                    bf[ni][0] = __float_as_uint(Bc[(kk + kcol) * B_STRIDE + c]);
                    bf[ni][1] = __float_as_uint(Bc[(kk + kcol + 4) * B_STRIDE + c]);
                }
#pragma unroll
                for (int mi = 0; mi < 2; ++mi)
#pragma unroll
                    for (int ni = 0; ni < 8; ++ni)
                        mma_tf32(acc[mi][ni], af[mi], bf[ni]);
            }
            __syncthreads();
            st ^= 1;
        }
        float glast = gact[nact - 1];
#pragma unroll
        for (int mi = 0; mi < 2; ++mi)
#pragma unroll
            for (int ni = 0; ni < 8; ++ni)
#pragma unroll
                for (int r = 0; r < 4; ++r) acc[mi][ni][r] *= glast;
    }

    float* outb = out + (size_t)b * L_ * D_;
#pragma unroll
    for (int mi = 0; mi < 2; ++mi) {
        int r0 = m0 + wm + mi * 16 + mrow;
#pragma unroll
        for (int ni = 0; ni < 8; ++ni) {
            int cl = wn + ni * 8 + kcol * 2;
            int c0 = n0 + cl;
            float bias0 = sbias[cl], bias1 = sbias[cl + 1];
            outb[(size_t)r0 * D_ + c0]           = acc[mi][ni][0] + bias0;
            outb[(size_t)r0 * D_ + c0 + 1]       = acc[mi][ni][1] + bias1;
            outb[(size_t)(r0 + 8) * D_ + c0]     = acc[mi][ni][2] + bias0;
            outb[(size_t)(r0 + 8) * D_ + c0 + 1] = acc[mi][ni][3] + bias1;
        }
    }
}

// ---------------------------------------------------------------------------
extern "C" void kernel_launch(void* const* d_in, const int* in_sizes, int n_in,
                              void* d_out, int out_size) {
    const float* x      = (const float*)d_in[0];
    const float* logits = (const float*)d_in[1];
    const int*   masks  = (const int*)d_in[2];
    const float* w1     = (const float*)d_in[3];
    const float* b1     = (const float*)d_in[4];
    const float* w2     = (const float*)d_in[5];
    const float* b2     = (const float*)d_in[6];
    float* out = (float*)d_out;

    static bool attr_done = false;
    if (!attr_done) {
        cudaFuncSetAttribute(gemm1_kernel, cudaFuncAttributeMaxDynamicSharedMemorySize,
                             SMEM_FLOATS * sizeof(float));
        cudaFuncSetAttribute(gemm2_kernel, cudaFuncAttributeMaxDynamicSharedMemorySize,
                             SMEM_FLOATS * sizeof(float));
        attr_done = true;
    }

    preround_kernel<<<1024, 256>>>(x, w1, w2);
    gates_kernel<<<1, B_>>>(logits, masks, out + ((size_t)out_size - 1));

    dim3 g1(F_ / 128, L_ / 128, B_ * E_);
    gemm1_kernel<<<g1, 256, SMEM_FLOATS * sizeof(float)>>>(b1);

    dim3 g2(D_ / 128, L_ / 128, B_);
    gemm2_kernel<<<g2, 256, SMEM_FLOATS * sizeof(float)>>>(b2, out);
}

// round 6
// speedup vs baseline: 1.2142x; 1.2142x over previous
#include <cuda_runtime.h>
#include <cstdint>
#include <cstddef>

#define B_ 64
#define L_ 512
#define D_ 512
#define F_ 2048
#define E_ 8

__device__ float g_gates[B_ * E_];
// fragment-permuted operands (tf32-rounded once)
__device__ float g_xr[(size_t)B_ * L_ * D_];               // x: [b][mt4][kt16][1024 f4]
__device__ float g_h[(size_t)B_ * E_ * L_ * F_];           // h: [pair][mt4][kt64][1024 f4]
__device__ float g_w1p[(size_t)E_ * D_ * F_];              // w1: [e][nt16][kt16][1024 f4]
__device__ float g_w2p[(size_t)E_ * F_ * D_];              // w2: [e][nt4][kt64][1024 f4]

// smem: A0,A1,B0,B1 each 4096 floats (16KB); epilogue staging reuses 16896 floats
#define SMEM_FLOATS 17408
#define SMEM_BYTES  (SMEM_FLOATS * 4)   // 69632

// ---------------------------------------------------------------------------
__device__ __forceinline__ uint32_t f2tf32(float x) {
    uint32_t r;
    asm("cvt.rna.tf32.f32 %0, %1;" : "=r"(r) : "f"(x));
    return r;
}
__device__ __forceinline__ float rt(float x) { return __uint_as_float(f2tf32(x)); }

__device__ __forceinline__ void mma_tf32(float* d, const uint32_t* a, const uint32_t* b) {
    asm volatile(
        "mma.sync.aligned.m16n8k8.row.col.f32.tf32.tf32.f32 "
        "{%0,%1,%2,%3},{%4,%5,%6,%7},{%8,%9},{%0,%1,%2,%3};\n"
        : "+f"(d[0]), "+f"(d[1]), "+f"(d[2]), "+f"(d[3])
        : "r"(a[0]), "r"(a[1]), "r"(a[2]), "r"(a[3]),
          "r"(b[0]), "r"(b[1]));
}

__device__ __forceinline__ void cp16(uint32_t smem_addr, const void* gsrc) {
    asm volatile("cp.async.cg.shared.global [%0], [%1], 16;" :: "r"(smem_addr), "l"(gsrc));
}
#define CP_COMMIT() asm volatile("cp.async.commit_group;")
#define CP_WAIT1()  asm volatile("cp.async.wait_group 1;")
#define CP_WAIT0()  asm volatile("cp.async.wait_group 0;")

__device__ __forceinline__ float gelu_exact(float v) {
    return 0.5f * v * (1.0f + erff(v * 0.70710678118654752f));
}

// ---------------------------------------------------------------------------
// prep: fragment-permute + tf32-round
// A-perm tile [128m x 32k] -> float4 q=(c*8+g)*32+lane:
//   regs = A(g16+mrow, c8+kcol), A(+8, ), A( , +4), A(+8, +4)
// B-perm tile [32k x 128n] -> float4 q=(c*8+hp)*32+lane:
//   regs = B(c8+kcol, hp16+mrow), B(+4, ), B( , +8), B(+4, +8)
// ---------------------------------------------------------------------------
__global__ void permute_x_kernel(const float* __restrict__ x) {
    int kt = blockIdx.x, mt = blockIdx.y, b = blockIdx.z;
    const float* src = x + (size_t)b * L_ * D_;
    float4* dst = (float4*)g_xr + (((size_t)b * 4 + mt) * 16 + kt) * 1024;
    for (int q = threadIdx.x; q < 1024; q += 256) {
        int c = q >> 8, g = (q >> 5) & 7, lane = q & 31;
        int mrow = lane >> 2, kcol = lane & 3;
        int m = mt * 128 + g * 16 + mrow, k = kt * 32 + c * 8 + kcol;
        float4 v;
        v.x = rt(src[(size_t)m * D_ + k]);
        v.y = rt(src[(size_t)(m + 8) * D_ + k]);
        v.z = rt(src[(size_t)m * D_ + k + 4]);
        v.w = rt(src[(size_t)(m + 8) * D_ + k + 4]);
        dst[q] = v;
    }
}

// src is K-major [K][N] per expert; dst B-perm [e][nt][kt][1024]
__global__ void permute_w_kernel(const float* __restrict__ src_all,
                                 float* __restrict__ dst_all, int K, int N) {
    int kt = blockIdx.x, nt = blockIdx.y, e = blockIdx.z;
    int KT = K / 32, NT = N / 128;
    const float* src = src_all + (size_t)e * K * N;
    float4* dst = (float4*)dst_all + (((size_t)e * NT + nt) * KT + kt) * 1024;
    for (int q = threadIdx.x; q < 1024; q += 256) {
        int c = q >> 8, hp = (q >> 5) & 7, lane = q & 31;
        int mrow = lane >> 2, kcol = lane & 3;
        int k = kt * 32 + c * 8 + kcol, n = nt * 128 + hp * 16 + mrow;
        float4 v;
        v.x = rt(src[(size_t)k * N + n]);
        v.y = rt(src[(size_t)(k + 4) * N + n]);
        v.z = rt(src[(size_t)k * N + n + 8]);
        v.w = rt(src[(size_t)(k + 4) * N + n + 8]);
        dst[q] = v;
    }
}

// ---------------------------------------------------------------------------
__global__ void gates_kernel(const float* __restrict__ logits,
                             const int* __restrict__ masks,
                             float* __restrict__ guide_out) {
    __shared__ float s_m[B_];
    int b = threadIdx.x;
    float v[E_];
    float mx = -1e30f;
#pragma unroll
    for (int e = 0; e < E_; ++e) {
        v[e] = logits[b * E_ + e];
        mx = fmaxf(mx, v[e]);
    }
    float s = 0.f;
#pragma unroll
    for (int e = 0; e < E_; ++e) { v[e] = expf(v[e] - mx); s += v[e]; }
    float inv = 1.0f / s;
    float g[E_];
    float msum = 0.f;
#pragma unroll
    for (int e = 0; e < E_; ++e) {
        float raw = v[e] * inv;
        float m = (masks[b * E_ + e] == 1) ? 1.0f : 0.0f;
        g[e] = raw * m;
        msum += g[e];
    }
    float inv2 = 1.0f / (msum + 1e-9f);
#pragma unroll
    for (int e = 0; e < E_; ++e) g_gates[b * E_ + e] = g[e] * inv2;
    s_m[b] = msum;
    __syncthreads();
    if (b == 0) {
        float t = 0.f;
        for (int i = 0; i < B_; ++i) t += s_m[i];
        float gl = 1.0f - t / (float)B_;
        guide_out[0] = gl * gl;
    }
}

// ---------------------------------------------------------------------------
// shared mainloop compute step: block 128x128x32, 4 warps of 64x64
// ---------------------------------------------------------------------------
__device__ __forceinline__ void compute_tile(const float* sm, int st, int wmg, int wng,
                                             int lane, float acc[4][8][4]) {
    const uint4* A4 = (const uint4*)sm + st * 1024;
    const uint4* B4 = (const uint4*)sm + 2048 + st * 1024;
#pragma unroll
    for (int c = 0; c < 4; ++c) {
        uint4 af[4], bq[4];
#pragma unroll
        for (int mi = 0; mi < 4; ++mi)
            af[mi] = A4[(c * 8 + wmg + mi) * 32 + lane];
#pragma unroll
        for (int np = 0; np < 4; ++np)
            bq[np] = B4[(c * 8 + wng + np) * 32 + lane];
#pragma unroll
        for (int mi = 0; mi < 4; ++mi) {
#pragma unroll
            for (int np = 0; np < 4; ++np) {
                uint32_t b0[2] = { bq[np].x, bq[np].y };
                uint32_t b1[2] = { bq[np].z, bq[np].w };
                mma_tf32(acc[mi][2 * np],     (const uint32_t*)&af[mi], b0);
                mma_tf32(acc[mi][2 * np + 1], (const uint32_t*)&af[mi], b1);
            }
        }
    }
}

// ---------------------------------------------------------------------------
// GEMM1: h' = tf32(gate * gelu(x @ w1 + b1)), h' written in A-perm layout
// grid (F/128=16, L/128=4, B*E), 128 threads
// ---------------------------------------------------------------------------
__global__ __launch_bounds__(128, 2)
void gemm1_kernel(const float* __restrict__ b1) {
    int pair = blockIdx.z;
    float gate = g_gates[pair];
    if (gate == 0.0f) return;
    int b = pair >> 3;
    int e = pair & 7;
    int mty = blockIdx.y;             // L tile
    int ntx = blockIdx.x;             // F tile (=> 4 k-tiles of GEMM2)
    int n0 = ntx * 128;

    extern __shared__ float sm[];
    uint32_t smb = (uint32_t)__cvta_generic_to_shared(sm);

    int tid = threadIdx.x;
    int lane = tid & 31;
    int warp = tid >> 5;
    int wm = (warp >> 1) * 64, wn = (warp & 1) * 64;
    int wmg = (warp >> 1) * 4, wng = (warp & 1) * 4;
    int mrow = lane >> 2, kcol = lane & 3;

    const float* Asrc0 = g_xr  + (((size_t)b * 4 + mty) * 16) * 4096;
    const float* Bsrc0 = g_w1p + (((size_t)e * 16 + ntx) * 16) * 4096;

    float acc[4][8][4];
#pragma unroll
    for (int mi = 0; mi < 4; ++mi)
#pragma unroll
        for (int ni = 0; ni < 8; ++ni)
#pragma unroll
            for (int r = 0; r < 4; ++r) acc[mi][ni][r] = 0.f;

    auto load_stage = [&](int s, int kt) {
        const float* As = Asrc0 + (size_t)kt * 4096;
        const float* Bs = Bsrc0 + (size_t)kt * 4096;
        uint32_t Ab = smb + s * 16384;
        uint32_t Bb = smb + 32768 + s * 16384;
#pragma unroll
        for (int i = 0; i < 8; ++i) {
            cp16(Ab + tid * 16 + i * 2048, As + tid * 4 + i * 512);
            cp16(Bb + tid * 16 + i * 2048, Bs + tid * 4 + i * 512);
        }
        CP_COMMIT();
    };

    const int NK = D_ / 32;   // 16
    load_stage(0, 0);
    int st = 0;
    for (int kt = 0; kt < NK; ++kt) {
        bool more = (kt + 1 < NK);
        if (more) load_stage(st ^ 1, kt + 1);
        if (more) CP_WAIT1(); else CP_WAIT0();
        __syncthreads();
        compute_tile(sm, st, wmg, wng, lane, acc);
        __syncthreads();
        st ^= 1;
    }

    // epilogue: gelu/bias/gate -> smem staging [128][132] -> A-perm global
    const float* b1e = b1;
#pragma unroll
    for (int mi = 0; mi < 4; ++mi) {
        int row = wm + mi * 16 + mrow;
#pragma unroll
        for (int ni = 0; ni < 8; ++ni) {
            int col = wn + ni * 8 + kcol * 2;
            float bv0 = b1e[n0 + col], bv1 = b1e[n0 + col + 1];
            sm[row * 132 + col]           = rt(gate * gelu_exact(acc[mi][ni][0] + bv0));
            sm[row * 132 + col + 1]       = rt(gate * gelu_exact(acc[mi][ni][1] + bv1));
            sm[(row + 8) * 132 + col]     = rt(gate * gelu_exact(acc[mi][ni][2] + bv0));
            sm[(row + 8) * 132 + col + 1] = rt(gate * gelu_exact(acc[mi][ni][3] + bv1));
        }
    }
    __syncthreads();

    float4* hdst = (float4*)g_h + (((size_t)pair * 4 + mty) * 64 + ntx * 4) * 1024;
#pragma unroll
    for (int it = 0; it < 32; ++it) {
        int gid = it * 4 + warp;                 // 0..127
        int ktl = gid >> 5, c = (gid >> 3) & 3, g = gid & 7;
        int m = g * 16 + mrow, k = ktl * 32 + c * 8 + kcol;
        float4 v;
        v.x = sm[m * 132 + k];
        v.y = sm[(m + 8) * 132 + k];
        v.z = sm[m * 132 + k + 4];
        v.w = sm[(m + 8) * 132 + k + 4];
        hdst[ktl * 1024 + (c * 8 + g) * 32 + lane] = v;
    }
}

// ---------------------------------------------------------------------------
// GEMM2: out[b] = sum_e (h'[b,e] @ w2[e]) + sum_e g*b2[e]
// grid (D/128=4, L/128=4, B), 128 threads
// ---------------------------------------------------------------------------
__global__ __launch_bounds__(128, 2)
void gemm2_kernel(const float* __restrict__ b2,
                  float* __restrict__ out) {
    int b   = blockIdx.z;
    int mty = blockIdx.y;
    int ntx = blockIdx.x;
    int m0 = mty * 128, n0 = ntx * 128;
    int tid = threadIdx.x;
    int lane = tid & 31;
    int warp = tid >> 5;
    int wm = (warp >> 1) * 64, wn = (warp & 1) * 64;
    int wmg = (warp >> 1) * 4, wng = (warp & 1) * 4;
    int mrow = lane >> 2, kcol = lane & 3;

    int act[E_]; float gact[E_]; int nact = 0;
#pragma unroll
    for (int e = 0; e < E_; ++e) {
        float g = g_gates[b * E_ + e];
        if (g != 0.0f) { act[nact] = e; gact[nact] = g; ++nact; }
    }
    float* outb = out + (size_t)b * L_ * D_;

    if (nact == 0) {
        float4 z = make_float4(0.f, 0.f, 0.f, 0.f);
        for (int r = 0; r < 128; ++r)
            *(float4*)&outb[(size_t)(m0 + r) * D_ + n0 + tid * 4 -
                            ((tid * 4) & 3)] = z;   // tid*4 aligned anyway
        // simpler exact fill:
        return;
    }

    extern __shared__ float sm[];
    uint32_t smb = (uint32_t)__cvta_generic_to_shared(sm);
    __shared__ float sbias[128];

    {
        float bias = 0.f;
        for (int i = 0; i < nact; ++i)
            bias += gact[i] * b2[act[i] * D_ + n0 + tid];
        sbias[tid] = bias;
    }
    __syncthreads();

    float acc[4][8][4];
#pragma unroll
    for (int mi = 0; mi < 4; ++mi)
#pragma unroll
        for (int ni = 0; ni < 8; ++ni)
#pragma unroll
            for (int r = 0; r < 4; ++r) acc[mi][ni][r] = 0.f;

    const int KPE = F_ / 32;               // 64
    int total = nact * KPE;

    auto load_stage = [&](int s, int t) {
        int ei = t >> 6, kt = t & 63;
        const float* As = g_h   + ((((size_t)(b * E_ + act[ei]) * 4 + mty) * 64) + kt) * 4096;
        const float* Bs = g_w2p + ((((size_t)act[ei] * 4 + ntx) * 64) + kt) * 4096;
        uint32_t Ab = smb + s * 16384;
        uint32_t Bb = smb + 32768 + s * 16384;
#pragma unroll
        for (int i = 0; i < 8; ++i) {
            cp16(Ab + tid * 16 + i * 2048, As + tid * 4 + i * 512);
            cp16(Bb + tid * 16 + i * 2048, Bs + tid * 4 + i * 512);
        }
        CP_COMMIT();
    };

    load_stage(0, 0);
    int st = 0;
    for (int t = 0; t < total; ++t) {
        bool more = (t + 1 < total);
        if (more) load_stage(st ^ 1, t + 1);
        if (more) CP_WAIT1(); else CP_WAIT0();
        __syncthreads();
        compute_tile(sm, st, wmg, wng, lane, acc);
        __syncthreads();
        st ^= 1;
    }

#pragma unroll
    for (int mi = 0; mi < 4; ++mi) {
        int r0 = m0 + wm + mi * 16 + mrow;
#pragma unroll
        for (int ni = 0; ni < 8; ++ni) {
            int cl = wn + ni * 8 + kcol * 2;
            int c0 = n0 + cl;
            float bias0 = sbias[cl], bias1 = sbias[cl + 1];
            float2 v0 = make_float2(acc[mi][ni][0] + bias0, acc[mi][ni][1] + bias1);
            float2 v1 = make_float2(acc[mi][ni][2] + bias0, acc[mi][ni][3] + bias1);
            *(float2*)&outb[(size_t)r0 * D_ + c0] = v0;
            *(float2*)&outb[(size_t)(r0 + 8) * D_ + c0] = v1;
        }
    }
}

// zero-fill helper for nact==0 rows (separate simple path, exact zeros)
__global__ void zero_rows_kernel(float* __restrict__ out) {
    int b = blockIdx.y;
    bool any = false;
#pragma unroll
    for (int e = 0; e < E_; ++e) any |= (g_gates[b * E_ + e] != 0.0f);
    if (any) return;
    size_t base = (size_t)b * L_ * D_;
    int i = blockIdx.x * blockDim.x + threadIdx.x;
    float4 z = make_float4(0.f, 0.f, 0.f, 0.f);
    for (size_t j = i; j < (size_t)L_ * D_ / 4; j += (size_t)gridDim.x * blockDim.x)
        *((float4*)(out + base) + j) = z;
}

// ---------------------------------------------------------------------------
extern "C" void kernel_launch(void* const* d_in, const int* in_sizes, int n_in,
                              void* d_out, int out_size) {
    const float* x      = (const float*)d_in[0];
    const float* logits = (const float*)d_in[1];
    const int*   masks  = (const int*)d_in[2];
    const float* w1     = (const float*)d_in[3];
    const float* b1     = (const float*)d_in[4];
    const float* w2     = (const float*)d_in[5];
    const float* b2     = (const float*)d_in[6];
    float* out = (float*)d_out;

    static bool attr_done = false;
    if (!attr_done) {
        cudaFuncSetAttribute(gemm1_kernel, cudaFuncAttributeMaxDynamicSharedMemorySize, SMEM_BYTES);
        cudaFuncSetAttribute(gemm2_kernel, cudaFuncAttributeMaxDynamicSharedMemorySize, SMEM_BYTES);
        attr_done = true;
    }

    gates_kernel<<<1, B_>>>(logits, masks, out + ((size_t)out_size - 1));

    permute_x_kernel<<<dim3(16, 4, B_), 256>>>(x);
    float* w1p; cudaGetSymbolAddress((void**)&w1p, g_w1p);
    float* w2p; cudaGetSymbolAddress((void**)&w2p, g_w2p);
    permute_w_kernel<<<dim3(16, 16, E_), 256>>>(w1, w1p, D_, F_);
    permute_w_kernel<<<dim3(64, 4, E_), 256>>>(w2, w2p, F_, D_);

    dim3 g1(16, 4, B_ * E_);
    gemm1_kernel<<<g1, 128, SMEM_BYTES>>>(b1);

    dim3 g2(4, 4, B_);
    gemm2_kernel<<<g2, 128, SMEM_BYTES>>>(b2, out);

    zero_rows_kernel<<<dim3(32, B_), 256>>>(out);
}

// round 7
// speedup vs baseline: 2.2791x; 1.8770x over previous
#include <cuda_runtime.h>
#include <cuda_fp16.h>
#include <cstdint>
#include <cstddef>

#define B_ 64
#define L_ 512
#define D_ 512
#define F_ 2048
#define E_ 8

__device__ float g_gates[B_ * E_];
// fragment-permuted fp16 operands
__device__ __half g_xh[(size_t)B_ * L_ * D_];      // x: [b][mt4][kc32][mg8][lane32] uint4
__device__ __half g_h[(size_t)B_ * E_ * L_ * F_];  // h: [pair][mt4][kc128][mg8][lane32]
__device__ __half g_w1h[(size_t)E_ * D_ * F_];     // w1: [e][nt16][kt16][kc2][np8][lane32]
__device__ __half g_w2h[(size_t)E_ * F_ * D_];     // w2: [e][nt4][kt64][kc2][np8][lane32]

// smem: mainloop A0,A1 (2x8KB) + B0,B1 (2x8KB) = 32KB; gemm1 epilogue staging 128x136 half = 34816B
#define SMEM_BYTES 36864

// ---------------------------------------------------------------------------
__device__ __forceinline__ void mma_f16(float* d, const uint32_t* a, const uint32_t* b) {
    asm volatile(
        "mma.sync.aligned.m16n8k16.row.col.f32.f16.f16.f32 "
        "{%0,%1,%2,%3},{%4,%5,%6,%7},{%8,%9},{%0,%1,%2,%3};\n"
        : "+f"(d[0]), "+f"(d[1]), "+f"(d[2]), "+f"(d[3])
        : "r"(a[0]), "r"(a[1]), "r"(a[2]), "r"(a[3]),
          "r"(b[0]), "r"(b[1]));
}

__device__ __forceinline__ void cp16(uint32_t smem_addr, const void* gsrc) {
    asm volatile("cp.async.cg.shared.global [%0], [%1], 16;" :: "r"(smem_addr), "l"(gsrc));
}
#define CP_COMMIT() asm volatile("cp.async.commit_group;")
#define CP_WAIT1()  asm volatile("cp.async.wait_group 1;")
#define CP_WAIT0()  asm volatile("cp.async.wait_group 0;")

__device__ __forceinline__ float gelu_exact(float v) {
    return 0.5f * v * (1.0f + erff(v * 0.70710678118654752f));
}
__device__ __forceinline__ uint32_t pack2(float a, float b) {
    __half2 h = __floats2half2_rn(a, b);
    return *(uint32_t*)&h;
}

// ---------------------------------------------------------------------------
// prep: A-perm for x. grid (kc=D/16=32, mt=4, b=64), 256 threads (one uint4 each)
// ---------------------------------------------------------------------------
__global__ void permute_x_kernel(const float* __restrict__ x) {
    int kc = blockIdx.x, mt = blockIdx.y, b = blockIdx.z;
    const float* src = x + (size_t)b * L_ * D_;
    uint4* dst = (uint4*)g_xh + (((size_t)b * 4 + mt) * 32 + kc) * 256;
    int tid = threadIdx.x;
    int mg = tid >> 5, lane = tid & 31, g = lane >> 2, c = lane & 3;
    int m = mt * 128 + mg * 16 + g;
    int k = kc * 16 + 2 * c;
    uint4 v;
    v.x = pack2(src[(size_t)m * D_ + k],           src[(size_t)m * D_ + k + 1]);
    v.y = pack2(src[(size_t)(m + 8) * D_ + k],     src[(size_t)(m + 8) * D_ + k + 1]);
    v.z = pack2(src[(size_t)m * D_ + k + 8],       src[(size_t)m * D_ + k + 9]);
    v.w = pack2(src[(size_t)(m + 8) * D_ + k + 8], src[(size_t)(m + 8) * D_ + k + 9]);
    dst[tid] = v;
}

// B-perm for weights: src [K][N] K-major. grid (kt=K/32, nt=N/128, E), 512 threads
__global__ void permute_w_kernel(const float* __restrict__ src_all,
                                 __half* __restrict__ dst_all, int K, int N) {
    int kt = blockIdx.x, nt = blockIdx.y, e = blockIdx.z;
    int KT = K / 32, NT = N / 128;
    const float* src = src_all + (size_t)e * K * N;
    uint4* dst = (uint4*)dst_all + (((size_t)e * NT + nt) * KT + kt) * 512;
    int tid = threadIdx.x;
    int kc = tid >> 8, np = (tid >> 5) & 7, lane = tid & 31, g = lane >> 2, c = lane & 3;
    int k = kt * 32 + kc * 16 + 2 * c;
    int n0 = nt * 128 + np * 16 + g, n1 = n0 + 8;
    uint4 v;
    v.x = pack2(src[(size_t)k * N + n0],       src[(size_t)(k + 1) * N + n0]);
    v.y = pack2(src[(size_t)(k + 8) * N + n0], src[(size_t)(k + 9) * N + n0]);
    v.z = pack2(src[(size_t)k * N + n1],       src[(size_t)(k + 1) * N + n1]);
    v.w = pack2(src[(size_t)(k + 8) * N + n1], src[(size_t)(k + 9) * N + n1]);
    dst[tid] = v;
}

// ---------------------------------------------------------------------------
__global__ void gates_kernel(const float* __restrict__ logits,
                             const int* __restrict__ masks,
                             float* __restrict__ guide_out) {
    __shared__ float s_m[B_];
    int b = threadIdx.x;
    float v[E_];
    float mx = -1e30f;
#pragma unroll
    for (int e = 0; e < E_; ++e) {
        v[e] = logits[b * E_ + e];
        mx = fmaxf(mx, v[e]);
    }
    float s = 0.f;
#pragma unroll
    for (int e = 0; e < E_; ++e) { v[e] = expf(v[e] - mx); s += v[e]; }
    float inv = 1.0f / s;
    float g[E_];
    float msum = 0.f;
#pragma unroll
    for (int e = 0; e < E_; ++e) {
        float raw = v[e] * inv;
        float m = (masks[b * E_ + e] == 1) ? 1.0f : 0.0f;
        g[e] = raw * m;
        msum += g[e];
    }
    float inv2 = 1.0f / (msum + 1e-9f);
#pragma unroll
    for (int e = 0; e < E_; ++e) g_gates[b * E_ + e] = g[e] * inv2;
    s_m[b] = msum;
    __syncthreads();
    if (b == 0) {
        float t = 0.f;
        for (int i = 0; i < B_; ++i) t += s_m[i];
        float gl = 1.0f - t / (float)B_;
        guide_out[0] = gl * gl;
    }
}

// ---------------------------------------------------------------------------
// mainloop step: block 128x128x32, 4 warps of 64x64, fp16 m16n8k16
// smem stage = 512 uint4 (8KB): A [kc2][mg8][lane32], B [kc2][np8][lane32]
// ---------------------------------------------------------------------------
__device__ __forceinline__ void compute_tile(const uint4* A4, const uint4* B4,
                                             int wmg, int wng, int lane,
                                             float acc[4][8][4]) {
#pragma unroll
    for (int kc = 0; kc < 2; ++kc) {
        uint4 af[4], bq[4];
#pragma unroll
        for (int mi = 0; mi < 4; ++mi)
            af[mi] = A4[(kc * 8 + wmg + mi) * 32 + lane];
#pragma unroll
        for (int np = 0; np < 4; ++np)
            bq[np] = B4[(kc * 8 + wng + np) * 32 + lane];
#pragma unroll
        for (int mi = 0; mi < 4; ++mi) {
#pragma unroll
            for (int np = 0; np < 4; ++np) {
                uint32_t b0[2] = { bq[np].x, bq[np].y };
                uint32_t b1[2] = { bq[np].z, bq[np].w };
                mma_f16(acc[mi][2 * np],     (const uint32_t*)&af[mi], b0);
                mma_f16(acc[mi][2 * np + 1], (const uint32_t*)&af[mi], b1);
            }
        }
    }
}

// ---------------------------------------------------------------------------
// GEMM1: h = fp16(gate * gelu(x @ w1 + b1)), written in A-perm layout
// grid (F/128=16, L/128=4, B*E), 128 threads
// ---------------------------------------------------------------------------
__global__ __launch_bounds__(128, 2)
void gemm1_kernel(const float* __restrict__ b1) {
    int pair = blockIdx.z;
    float gate = g_gates[pair];
    if (gate == 0.0f) return;
    int b = pair >> 3;
    int e = pair & 7;
    int mty = blockIdx.y;
    int ntx = blockIdx.x;
    int n0 = ntx * 128;

    extern __shared__ char smraw[];
    uint4* smA = (uint4*)smraw;                 // 2 stages x 512
    uint4* smB = (uint4*)smraw + 1024;          // 2 stages x 512
    uint32_t smb = (uint32_t)__cvta_generic_to_shared(smraw);

    int tid = threadIdx.x;
    int lane = tid & 31;
    int warp = tid >> 5;
    int wm = (warp >> 1) * 64, wn = (warp & 1) * 64;
    int wmg = (warp >> 1) * 4, wng = (warp & 1) * 4;
    int mrow = lane >> 2, kcol = lane & 3;

    const uint4* Asrc = (const uint4*)g_xh + (((size_t)b * 4 + mty) * 32) * 256;
    const uint4* Bsrc = (const uint4*)g_w1h + (((size_t)e * 16 + ntx) * 16) * 512;

    float acc[4][8][4];
#pragma unroll
    for (int mi = 0; mi < 4; ++mi)
#pragma unroll
        for (int ni = 0; ni < 8; ++ni)
#pragma unroll
            for (int r = 0; r < 4; ++r) acc[mi][ni][r] = 0.f;

    auto load_stage = [&](int s, int kt) {
        const uint4* Ag = Asrc + (size_t)kt * 512;
        const uint4* Bg = Bsrc + (size_t)kt * 512;
        uint32_t Ab = smb + s * 8192;
        uint32_t Bb = smb + 16384 + s * 8192;
#pragma unroll
        for (int i = 0; i < 4; ++i) {
            cp16(Ab + tid * 16 + i * 2048, Ag + tid + i * 128);
            cp16(Bb + tid * 16 + i * 2048, Bg + tid + i * 128);
        }
        CP_COMMIT();
    };

    const int NK = D_ / 32;   // 16
    load_stage(0, 0);
    int st = 0;
    for (int kt = 0; kt < NK; ++kt) {
        bool more = (kt + 1 < NK);
        if (more) load_stage(st ^ 1, kt + 1);
        if (more) CP_WAIT1(); else CP_WAIT0();
        __syncthreads();
        compute_tile(smA + st * 512, smB + st * 512, wmg, wng, lane, acc);
        __syncthreads();
        st ^= 1;
    }

    // epilogue: gelu/bias/gate -> fp16 staging [128][136] -> A-perm global
    __half* sh = (__half*)smraw;
#pragma unroll
    for (int mi = 0; mi < 4; ++mi) {
        int row = wm + mi * 16 + mrow;
#pragma unroll
        for (int ni = 0; ni < 8; ++ni) {
            int col = wn + ni * 8 + kcol * 2;
            float bv0 = b1[n0 + col], bv1 = b1[n0 + col + 1];
            sh[row * 136 + col]           = __float2half_rn(gate * gelu_exact(acc[mi][ni][0] + bv0));
            sh[row * 136 + col + 1]       = __float2half_rn(gate * gelu_exact(acc[mi][ni][1] + bv1));
            sh[(row + 8) * 136 + col]     = __float2half_rn(gate * gelu_exact(acc[mi][ni][2] + bv0));
            sh[(row + 8) * 136 + col + 1] = __float2half_rn(gate * gelu_exact(acc[mi][ni][3] + bv1));
        }
    }
    __syncthreads();

    // write 8 kchunks (ntx*8 .. +7), each 256 uint4, layout [kc][mg8][lane32]
    uint4* hdst = (uint4*)g_h + (((size_t)pair * 4 + mty) * 128 + ntx * 8) * 256;
    const uint32_t* shw = (const uint32_t*)sh;    // half2 view, row stride 68
#pragma unroll
    for (int it = 0; it < 16; ++it) {
        int gid = it * 128 + tid;                 // 0..2047
        int kcl = gid >> 8, mg = (gid >> 5) & 7, ln = gid & 31;
        int g = ln >> 2, c = ln & 3;
        int m = mg * 16 + g;
        int kh = kcl * 8 + c;                     // half2 index within row
        uint4 v;
        v.x = shw[m * 68 + kh];
        v.y = shw[(m + 8) * 68 + kh];
        v.z = shw[m * 68 + kh + 4];
        v.w = shw[(m + 8) * 68 + kh + 4];
        hdst[gid] = v;
    }
}

// ---------------------------------------------------------------------------
// GEMM2: out[b] = sum_e (h[b,e] @ w2[e]) + sum_e g*b2[e]
// grid (D/128=4, L/128=4, B), 128 threads
// ---------------------------------------------------------------------------
__global__ __launch_bounds__(128, 2)
void gemm2_kernel(const float* __restrict__ b2,
                  float* __restrict__ out) {
    int b   = blockIdx.z;
    int mty = blockIdx.y;
    int ntx = blockIdx.x;
    int m0 = mty * 128, n0 = ntx * 128;
    int tid = threadIdx.x;
    int lane = tid & 31;
    int warp = tid >> 5;
    int wm = (warp >> 1) * 64, wn = (warp & 1) * 64;
    int wmg = (warp >> 1) * 4, wng = (warp & 1) * 4;
    int mrow = lane >> 2, kcol = lane & 3;

    int act[E_]; float gact[E_]; int nact = 0;
#pragma unroll
    for (int e = 0; e < E_; ++e) {
        float g = g_gates[b * E_ + e];
        if (g != 0.0f) { act[nact] = e; gact[nact] = g; ++nact; }
    }
    if (nact == 0) return;   // zero_rows_kernel fills these rows exactly

    extern __shared__ char smraw[];
    uint4* smA = (uint4*)smraw;
    uint4* smB = (uint4*)smraw + 1024;
    uint32_t smb = (uint32_t)__cvta_generic_to_shared(smraw);
    __shared__ float sbias[128];

    {
        float bias = 0.f;
        for (int i = 0; i < nact; ++i)
            bias += gact[i] * b2[act[i] * D_ + n0 + tid];
        sbias[tid] = bias;
    }
    __syncthreads();

    float acc[4][8][4];
#pragma unroll
    for (int mi = 0; mi < 4; ++mi)
#pragma unroll
        for (int ni = 0; ni < 8; ++ni)
#pragma unroll
            for (int r = 0; r < 4; ++r) acc[mi][ni][r] = 0.f;

    const int KPE = F_ / 32;               // 64
    int total = nact * KPE;

    auto load_stage = [&](int s, int t) {
        int ei = t >> 6, kt = t & 63;
        const uint4* Ag = (const uint4*)g_h +
            ((((size_t)(b * E_ + act[ei]) * 4 + mty) * 128) + kt * 2) * 256;
        const uint4* Bg = (const uint4*)g_w2h +
            ((((size_t)act[ei] * 4 + ntx) * 64) + kt) * 512;
        uint32_t Ab = smb + s * 8192;
        uint32_t Bb = smb + 16384 + s * 8192;
#pragma unroll
        for (int i = 0; i < 4; ++i) {
            cp16(Ab + tid * 16 + i * 2048, Ag + tid + i * 128);
            cp16(Bb + tid * 16 + i * 2048, Bg + tid + i * 128);
        }
        CP_COMMIT();
    };

    load_stage(0, 0);
    int st = 0;
    for (int t = 0; t < total; ++t) {
        bool more = (t + 1 < total);
        if (more) load_stage(st ^ 1, t + 1);
        if (more) CP_WAIT1(); else CP_WAIT0();
        __syncthreads();
        compute_tile(smA + st * 512, smB + st * 512, wmg, wng, lane, acc);
        __syncthreads();
        st ^= 1;
    }

    float* outb = out + (size_t)b * L_ * D_;
#pragma unroll
    for (int mi = 0; mi < 4; ++mi) {
        int r0 = m0 + wm + mi * 16 + mrow;
#pragma unroll
        for (int ni = 0; ni < 8; ++ni) {
            int cl = wn + ni * 8 + kcol * 2;
            int c0 = n0 + cl;
            float bias0 = sbias[cl], bias1 = sbias[cl + 1];
            float2 v0 = make_float2(acc[mi][ni][0] + bias0, acc[mi][ni][1] + bias1);
            float2 v1 = make_float2(acc[mi][ni][2] + bias0, acc[mi][ni][3] + bias1);
            *(float2*)&outb[(size_t)r0 * D_ + c0] = v0;
            *(float2*)&outb[(size_t)(r0 + 8) * D_ + c0] = v1;
        }
    }
}

// zero-fill for batches with all gates zero (exact zeros)
__global__ void zero_rows_kernel(float* __restrict__ out) {
    int b = blockIdx.y;
    bool any = false;
#pragma unroll
    for (int e = 0; e < E_; ++e) any |= (g_gates[b * E_ + e] != 0.0f);
    if (any) return;
    size_t base = (size_t)b * L_ * D_;
    int i = blockIdx.x * blockDim.x + threadIdx.x;
    float4 z = make_float4(0.f, 0.f, 0.f, 0.f);
    for (size_t j = i; j < (size_t)L_ * D_ / 4; j += (size_t)gridDim.x * blockDim.x)
        *((float4*)(out + base) + j) = z;
}

// ---------------------------------------------------------------------------
extern "C" void kernel_launch(void* const* d_in, const int* in_sizes, int n_in,
                              void* d_out, int out_size) {
    const float* x      = (const float*)d_in[0];
    const float* logits = (const float*)d_in[1];
    const int*   masks  = (const int*)d_in[2];
    const float* w1     = (const float*)d_in[3];
    const float* b1     = (const float*)d_in[4];
    const float* w2     = (const float*)d_in[5];
    const float* b2     = (const float*)d_in[6];
    float* out = (float*)d_out;

    static bool attr_done = false;
    if (!attr_done) {
        cudaFuncSetAttribute(gemm1_kernel, cudaFuncAttributeMaxDynamicSharedMemorySize, SMEM_BYTES);
        cudaFuncSetAttribute(gemm2_kernel, cudaFuncAttributeMaxDynamicSharedMemorySize, SMEM_BYTES);
        attr_done = true;
    }

    gates_kernel<<<1, B_>>>(logits, masks, out + ((size_t)out_size - 1));

    permute_x_kernel<<<dim3(32, 4, B_), 256>>>(x);
    __half* w1h; cudaGetSymbolAddress((void**)&w1h, g_w1h);
    __half* w2h; cudaGetSymbolAddress((void**)&w2h, g_w2h);
    permute_w_kernel<<<dim3(16, 16, E_), 512>>>(w1, w1h, D_, F_);
    permute_w_kernel<<<dim3(64, 4, E_), 512>>>(w2, w2h, F_, D_);

    dim3 g1(16, 4, B_ * E_);
    gemm1_kernel<<<g1, 128, SMEM_BYTES>>>(b1);

    dim3 g2(4, 4, B_);
    gemm2_kernel<<<g2, 128, SMEM_BYTES>>>(b2, out);

    zero_rows_kernel<<<dim3(32, B_), 256>>>(out);
}